// round 5
// baseline (speedup 1.0000x reference)
#include <cuda_runtime.h>

#define SEQ       128
#define BATCH     512
#define INPUT_DIM 128
#define HIDDEN    128
#define NQ        8

typedef unsigned long long u64;

__device__ __forceinline__ u64 pk(float lo, float hi) {
    u64 r; asm("mov.b64 %0, {%1, %2};" : "=l"(r) : "f"(lo), "f"(hi)); return r;
}
__device__ __forceinline__ void upk(u64 v, float& lo, float& hi) {
    asm("mov.b64 {%0, %1}, %2;" : "=f"(lo), "=f"(hi) : "l"(v));
}
#define MUL2(o,a,b)   asm("mul.rn.f32x2 %0, %1, %2;"     : "=l"(o) : "l"(a), "l"(b))
#define FMA2(o,a,b,c) asm("fma.rn.f32x2 %0, %1, %2, %3;" : "=l"(o) : "l"(a), "l"(b), "l"(c))

__device__ __forceinline__ void cmul(float& orr, float& oi,
                                     float ar, float ai, float br, float bi) {
    orr = fmaf(ar, br, -ai * bi);
    oi  = fmaf(ar, bi,  ai * br);
}

__global__ __launch_bounds__(256, 4)
void qlstm_all(const float* __restrict__ inputs,  // [SEQ,BATCH,INPUT_DIM]
               const float* __restrict__ Wq,      // [32,256] rows 0..7 used
               const float* __restrict__ bq,
               const float* __restrict__ pf,
               const float* __restrict__ pi_,
               const float* __restrict__ pg,
               const float* __restrict__ po,
               const float* __restrict__ Wf, const float* __restrict__ bf,
               const float* __restrict__ Wi, const float* __restrict__ bi,
               const float* __restrict__ Wg, const float* __restrict__ bg,
               const float* __restrict__ Wo, const float* __restrict__ bo,
               float* __restrict__ out)
{
    const int b    = blockIdx.x;
    const int tid  = threadIdx.x;
    const int wid  = tid >> 5;
    const int lane = tid & 31;
    const int g    = wid >> 1;   // gate 0..3 (f,i,g,o)
    const int u    = wid & 1;    // half of the state (k bit 7)

    __shared__ float sWq[8 * 256];            // 8KB
    __shared__ float sWgT[4][NQ][HIDDEN];     // 16KB transposed
    __shared__ float sC0[4][NQ], sS0[4][NQ];  // d0 RY constants (folded into init)
    __shared__ float sRc[4][NQ], sRs[4][NQ];  // d1 RY constants
    __shared__ float sBq[8];
    __shared__ float comb[256];
    __shared__ float qin[8];
    __shared__ float sWz[8][8];               // [warp][p] Walsh partials
    __shared__ u64  xch[4][8][32];            // [r][warp][lane] exchange (8KB)

    // ---------- one-time setup ----------
    for (int i = tid; i < 8 * 256; i += 256) sWq[i] = Wq[i];
    for (int i = tid; i < HIDDEN * NQ; i += 256) {
        int h = i >> 3, w = i & 7;
        sWgT[0][w][h] = Wf[i]; sWgT[1][w][h] = Wi[i];
        sWgT[2][w][h] = Wg[i]; sWgT[3][w][h] = Wo[i];
    }
    if (tid < 8) sBq[tid] = bq[tid];

    if (u == 0 && lane < 16) {
        const float* prm = (g == 0) ? pf : (g == 1) ? pi_ : (g == 2) ? pg : po;
        float c, s;
        __sincosf(0.5f * prm[lane], &s, &c);
        if (lane < 8) { sC0[g][lane] = c;     sS0[g][lane] = s;     }
        else          { sRc[g][lane - 8] = c; sRs[g][lane - 8] = s; }
    }

    float bfr = 0.f, bir = 0.f, bgr = 0.f, bor = 0.f;
    if (tid < 128) { bfr = bf[tid]; bir = bi[tid]; bgr = bg[tid]; bor = bo[tid]; }

    float hreg = 0.f, creg = 0.f;
    const float* inb = inputs + (size_t)b * INPUT_DIM;
    float xcur = (tid < 128) ? inb[tid] : 0.f;
    __syncthreads();

    for (int t = 0; t < SEQ; t++) {
        if (tid < 128) {
            comb[tid]       = xcur;
            comb[128 + tid] = hreg;
        }
        float xnext = 0.f;
        if (tid < 128 && t + 1 < SEQ)
            xnext = inb[(size_t)(t + 1) * BATCH * INPUT_DIM + tid];
        __syncthreads();   // A: comb visible

        // ---- q_in: warp wid -> Wq row wid ----
        {
            const float* w0 = sWq + wid * 256;
            float a0 = 0.f;
            #pragma unroll
            for (int j = 0; j < 8; j++) {
                int idx = lane + 32 * j;
                a0 = fmaf(comb[idx], w0[idx], a0);
            }
            #pragma unroll
            for (int o = 16; o; o >>= 1)
                a0 += __shfl_xor_sync(0xffffffffu, a0, o);
            if (lane == 0) qin[wid] = a0 + sBq[wid];
        }
        __syncthreads();   // B: qin visible

        // ---- init: product state after RX + first RY layer (folded) ----
        // k = (u<<7)|(lane<<2)|r ; wire w <-> k bit 7-w
        // wire 0 <-> u ; wires 1..5 <-> lane bits 4..0 ; wires 6,7 <-> r bits 1,0
        float Pr, Pi;
        {
            float st_, ct_;
            __sincosf(0.5f * qin[0], &st_, &ct_);
            float cf = sC0[g][0], sf = sS0[g][0];
            if (u) { Pr = sf * ct_; Pi = -cf * st_; }
            else   { Pr = cf * ct_; Pi =  sf * st_; }
        }
        #pragma unroll
        for (int w = 1; w < 6; w++) {
            float st_, ct_;
            __sincosf(0.5f * qin[w], &st_, &ct_);
            float cf = sC0[g][w], sf = sS0[g][w];
            int s = (lane >> (5 - w)) & 1;
            float xr = s ? sf * ct_ : cf * ct_;
            float xi = s ? -cf * st_ : sf * st_;
            float nr, ni;
            cmul(nr, ni, Pr, Pi, xr, xi);
            Pr = nr; Pi = ni;
        }
        float A6r, A6i, B6r, B6i, A7r, A7i, B7r, B7i;
        {
            float st_, ct_;
            __sincosf(0.5f * qin[6], &st_, &ct_);
            float cf = sC0[g][6], sf = sS0[g][6];
            A6r = cf * ct_;  A6i = sf * st_;
            B6r = sf * ct_;  B6i = -cf * st_;
            __sincosf(0.5f * qin[7], &st_, &ct_);
            cf = sC0[g][7]; sf = sS0[g][7];
            A7r = cf * ct_;  A7i = sf * st_;
            B7r = sf * ct_;  B7i = -cf * st_;
        }
        u64 st[4];
        #pragma unroll
        for (int r = 0; r < 4; r++) {
            float xr = (r & 2) ? B6r : A6r, xi = (r & 2) ? B6i : A6i; // wire6 = r bit1
            float yr = (r & 1) ? B7r : A7r, yi = (r & 1) ? B7i : A7i; // wire7 = r bit0
            float Tr, Ti, fr, fi;
            cmul(Tr, Ti, xr, xi, yr, yi);
            cmul(fr, fi, Pr, Pi, Tr, Ti);
            st[r] = pk(fr, fi);
        }

        // ---- d1 RY sweep (CNOT chains fused as Gray remap) ----
        // sublayer w=0 (p=7): pairMask=0xC0 -> cross-warp (u) + lane bit4
        {
            const float rc = sRc[g][0], rs = sRs[g][0];
            #pragma unroll
            for (int r = 0; r < 4; r++) xch[r][wid][lane] = st[r];
            __syncthreads();   // D: exchange visible
            float sgn = u ? rs : -rs;      // parity(k & 0x80) = u
            u64 rc2 = pk(rc, rc), co = pk(sgn, sgn);
            #pragma unroll
            for (int r = 0; r < 4; r++) {
                u64 v = xch[r][wid ^ 1][lane ^ 0x10];
                u64 tmp;
                MUL2(tmp, rc2, st[r]);
                FMA2(st[r], co, v, tmp);
            }
        }
        // sublayers w=1..7 (p=6..0): in-warp
        #pragma unroll
        for (int w = 1; w < 8; w++) {
            const int p = 7 - w;
            const float rc = sRc[g][w], rs = sRs[g][w];
            const int pairMask = (p > 0) ? (3 << (p - 1)) : 1;
            const int sideMask = (0xFF << p) & 0xFF;
            const int laneXor  = (pairMask >> 2) & 31;
            const int localXor = pairMask & 3;
            const int sideLane = (sideMask >> 2) & 31;
            const int sideR    = sideMask & 3;

            // parity(k & sideMask) = u ^ parity(lane&sideLane) ^ parity(r&sideR)
            int bpar = (u ^ (__popc(lane & sideLane) & 1)) & 1;
            float base = bpar ? rs : -rs;
            u64 rc2 = pk(rc, rc);
            u64 cp  = pk(base, base);
            u64 cn  = pk(-base, -base);

            u64 prt[4];
            #pragma unroll
            for (int r = 0; r < 4; r++) {
                u64 v = st[r ^ localXor];
                if (laneXor) v = __shfl_xor_sync(0xffffffffu, v, laneXor);
                prt[r] = v;
            }
            #pragma unroll
            for (int r = 0; r < 4; r++) {
                const int pir = __popc(r & sideR) & 1;   // compile-time
                u64 coef = pir ? cn : cp;
                u64 tmp;
                MUL2(tmp, rc2, st[r]);
                FMA2(st[r], coef, prt[r], tmp);
            }
        }

        // ---- Z expectations: local 2-bit Walsh + 5-level lane butterfly ----
        float prob[4];
        #pragma unroll
        for (int r = 0; r < 4; r++) {
            float re, im;
            upk(st[r], re, im);
            prob[r] = fmaf(re, re, im * im);
        }
        float SA = (prob[0] + prob[1]) + (prob[2] + prob[3]);   // local mask 0
        float S0 = (prob[0] - prob[1]) + (prob[2] - prob[3]);   // local mask 1 (r bit0)
        float S1 = (prob[0] + prob[1]) - (prob[2] + prob[3]);   // local mask 2 (r bit1)

        #pragma unroll
        for (int i = 0; i < 5; i++) {
            const int o = 1 << i;
            float pA = __shfl_xor_sync(0xffffffffu, SA, o);
            float p0 = __shfl_xor_sync(0xffffffffu, S0, o);
            float p1 = __shfl_xor_sync(0xffffffffu, S1, o);
            if ((lane >> i) & 1) { SA = pA - SA; S0 = p0 - S0; S1 = p1 - S1; }
            else                 { SA = SA + pA; S0 = S0 + p0; S1 = S1 + p1; }
        }
        // per-p lane targets: mz=(0x55<<p)&0xFF; lane=(mz>>2)&31, local mask mz&3
        if (lane == 0x15) { sWz[wid][0] = S0; sWz[wid][2] = SA; }
        if (lane == 0x0A) { sWz[wid][1] = S1; sWz[wid][3] = SA; }
        if (lane == 0x14) sWz[wid][4] = SA;
        if (lane == 0x08) sWz[wid][5] = SA;
        if (lane == 0x10) sWz[wid][6] = SA;
        if (lane == 0x00) sWz[wid][7] = SA;
        __syncthreads();   // C: sWz visible

        // ---- gate projections + LSTM update (tid < 128 <-> hidden unit tid) ----
        if (tid < 128) {
            float accf = bfr, acci = bir, accg = bgr, acco = bor;
            #pragma unroll
            for (int w = 0; w < NQ; w++) {
                const int p = 7 - w;
                const float sgnB = (p & 1) ? -1.f : 1.f;   // mz bit7 set for odd p
                float zf = fmaf(sgnB, sWz[1][p], sWz[0][p]);
                float zi = fmaf(sgnB, sWz[3][p], sWz[2][p]);
                float zg = fmaf(sgnB, sWz[5][p], sWz[4][p]);
                float zo = fmaf(sgnB, sWz[7][p], sWz[6][p]);
                accf = fmaf(zf, sWgT[0][w][tid], accf);
                acci = fmaf(zi, sWgT[1][w][tid], acci);
                accg = fmaf(zg, sWgT[2][w][tid], accg);
                acco = fmaf(zo, sWgT[3][w][tid], acco);
            }
            float fg = __fdividef(1.f, 1.f + __expf(-accf));
            float ig = __fdividef(1.f, 1.f + __expf(-acci));
            float e2 = __expf(2.f * accg);
            float gg = __fdividef(e2 - 1.f, e2 + 1.f);
            float og = __fdividef(1.f, 1.f + __expf(-acco));

            creg = fmaf(fg, creg, ig * gg);
            float e2c = __expf(2.f * creg);
            hreg = og * __fdividef(e2c - 1.f, e2c + 1.f);

            out[(size_t)t * BATCH * HIDDEN + (size_t)b * HIDDEN + tid] = hreg;
        }
        xcur = xnext;
    }

    // ---- final hx, cx ----
    if (tid < 128) {
        size_t base = (size_t)SEQ * BATCH * HIDDEN;
        out[base + (size_t)b * HIDDEN + tid] = hreg;
        out[base + (size_t)BATCH * HIDDEN + (size_t)b * HIDDEN + tid] = creg;
    }
}

extern "C" void kernel_launch(void* const* d_in, const int* in_sizes, int n_in,
                              void* d_out, int out_size)
{
    const float* inputs = (const float*)d_in[0];
    const float* Wq     = (const float*)d_in[1];
    const float* bq     = (const float*)d_in[2];
    const float* pf     = (const float*)d_in[3];
    const float* pi_    = (const float*)d_in[4];
    const float* pg     = (const float*)d_in[5];
    const float* po     = (const float*)d_in[6];
    const float* Wf     = (const float*)d_in[7];
    const float* bf     = (const float*)d_in[8];
    const float* Wi     = (const float*)d_in[9];
    const float* bi     = (const float*)d_in[10];
    const float* Wg     = (const float*)d_in[11];
    const float* bg     = (const float*)d_in[12];
    const float* Wo     = (const float*)d_in[13];
    const float* bo     = (const float*)d_in[14];
    float* out = (float*)d_out;

    qlstm_all<<<BATCH, 256>>>(inputs, Wq, bq, pf, pi_, pg, po,
                              Wf, bf, Wi, bi, Wg, bg, Wo, bo, out);
}

// round 6
// speedup vs baseline: 1.6809x; 1.6809x over previous
#include <cuda_runtime.h>

#define SEQ       128
#define BATCH     512
#define INPUT_DIM 128
#define HIDDEN    128
#define NQ        8

typedef unsigned long long u64;

__device__ __forceinline__ u64 pk(float lo, float hi) {
    u64 r; asm("mov.b64 %0, {%1, %2};" : "=l"(r) : "f"(lo), "f"(hi)); return r;
}
__device__ __forceinline__ void upk(u64 v, float& lo, float& hi) {
    asm("mov.b64 {%0, %1}, %2;" : "=f"(lo), "=f"(hi) : "l"(v));
}
#define MUL2(o,a,b)   asm("mul.rn.f32x2 %0, %1, %2;"     : "=l"(o) : "l"(a), "l"(b))
#define FMA2(o,a,b,c) asm("fma.rn.f32x2 %0, %1, %2, %3;" : "=l"(o) : "l"(a), "l"(b), "l"(c))

__device__ __forceinline__ void cmul(float& orr, float& oi,
                                     float ar, float ai, float br, float bi) {
    orr = fmaf(ar, br, -ai * bi);
    oi  = fmaf(ar, bi,  ai * br);
}

__global__ __launch_bounds__(128, 4)
void qlstm_all(const float* __restrict__ inputs,  // [SEQ,BATCH,INPUT_DIM]
               const float* __restrict__ Wq,      // [32,256] rows 0..7 used
               const float* __restrict__ bq,
               const float* __restrict__ pf,
               const float* __restrict__ pi_,
               const float* __restrict__ pg,
               const float* __restrict__ po,
               const float* __restrict__ Wf, const float* __restrict__ bf,
               const float* __restrict__ Wi, const float* __restrict__ bi,
               const float* __restrict__ Wg, const float* __restrict__ bg,
               const float* __restrict__ Wo, const float* __restrict__ bo,
               float* __restrict__ out)
{
    const int b    = blockIdx.x;
    const int tid  = threadIdx.x;
    const int wid  = tid >> 5;
    const int lane = tid & 31;

    __shared__ float4 sWq4[512];            // 8KB: rows 0..7 of Wq as float4
    __shared__ float4 sWg4[NQ][HIDDEN];     // 16KB: (f,i,g,o) per (wire,hidden)
    __shared__ float sC0[4][NQ], sS0[4][NQ];   // d0 RY constants (folded into init)
    __shared__ float sRc[4][NQ], sRs[4][NQ];   // d1 RY constants
    __shared__ float sBq[8];
    __shared__ float4 comb4[2][64];         // double-buffered [x;h]
    __shared__ float4 qin4[2][2];           // 8 q_in values as 2 float4
    __shared__ float4 zsh4[2][NQ];          // per wire: (zf,zi,zg,zo)

    // ---------- one-time setup ----------
    {
        const float4* Wq4 = (const float4*)Wq;
        for (int i = tid; i < 512; i += 128) sWq4[i] = Wq4[i];
        for (int i = tid; i < HIDDEN * NQ; i += 128) {
            int h = i >> 3, w = i & 7;
            sWg4[w][h] = make_float4(Wf[i], Wi[i], Wg[i], Wo[i]);
        }
        if (tid < 8) sBq[tid] = bq[tid];

        const float* prm = (wid == 0) ? pf : (wid == 1) ? pi_ : (wid == 2) ? pg : po;
        if (lane < 16) {
            float c, s;
            __sincosf(0.5f * prm[lane], &s, &c);
            if (lane < 8) { sC0[wid][lane] = c;     sS0[wid][lane] = s;     }
            else          { sRc[wid][lane - 8] = c; sRs[wid][lane - 8] = s; }
        }
    }

    const float bfr = bf[tid], bir = bi[tid], bgr = bg[tid], bor = bo[tid];

    float hreg = 0.f, creg = 0.f;
    const float* inb = inputs + (size_t)b * INPUT_DIM;
    float xcur = inb[tid];                 // prefetch t=0
    __syncthreads();

    for (int t = 0; t < SEQ; t++) {
        const int buf = t & 1;

        {
            float* combS = (float*)comb4[buf];
            combS[tid]       = xcur;
            combS[128 + tid] = hreg;
        }
        float xnext = 0.f;
        if (t + 1 < SEQ) xnext = inb[(size_t)(t + 1) * BATCH * INPUT_DIM + tid];
        __syncthreads();   // A: comb visible

        // ---- q_in = combined @ Wq[:8].T + bq[:8] (warp wid -> rows 2wid, 2wid+1) ----
        {
            const float4* w0 = sWq4 + (2 * wid) * 64;
            const float4* w1 = w0 + 64;
            float4 c0 = comb4[buf][lane];
            float4 c1 = comb4[buf][32 + lane];
            float4 wa = w0[lane], wb = w0[32 + lane];
            float4 wc = w1[lane], wd = w1[32 + lane];
            float a0 = c0.x * wa.x;
            a0 = fmaf(c0.y, wa.y, a0); a0 = fmaf(c0.z, wa.z, a0); a0 = fmaf(c0.w, wa.w, a0);
            a0 = fmaf(c1.x, wb.x, a0); a0 = fmaf(c1.y, wb.y, a0);
            a0 = fmaf(c1.z, wb.z, a0); a0 = fmaf(c1.w, wb.w, a0);
            float a1 = c0.x * wc.x;
            a1 = fmaf(c0.y, wc.y, a1); a1 = fmaf(c0.z, wc.z, a1); a1 = fmaf(c0.w, wc.w, a1);
            a1 = fmaf(c1.x, wd.x, a1); a1 = fmaf(c1.y, wd.y, a1);
            a1 = fmaf(c1.z, wd.z, a1); a1 = fmaf(c1.w, wd.w, a1);
            #pragma unroll
            for (int o = 16; o; o >>= 1) {
                a0 += __shfl_xor_sync(0xffffffffu, a0, o);
                a1 += __shfl_xor_sync(0xffffffffu, a1, o);
            }
            if (lane == 0) {
                float* q = (float*)qin4[buf];
                q[2 * wid]     = a0 + sBq[2 * wid];
                q[2 * wid + 1] = a1 + sBq[2 * wid + 1];
            }
        }
        __syncthreads();   // B: qin visible

        float4 q03 = qin4[buf][0], q47 = qin4[buf][1];
        const float q[8] = {q03.x, q03.y, q03.z, q03.w, q47.x, q47.y, q47.z, q47.w};

        // ---- init: product state after RX + first RY layer (folded) ----
        // A_w = (cf*ct, sf*st), B_w = (sf*ct, -cf*st); k=(lane<<3)|r, wire w <-> bit 7-w
        float Are[NQ], Aim[NQ], Bre[NQ], Bim[NQ];
        #pragma unroll
        for (int w = 0; w < NQ; w++) {
            float st_, ct_;
            __sincosf(0.5f * q[w], &st_, &ct_);
            float cf = sC0[wid][w], sf = sS0[wid][w];
            Are[w] = cf * ct_;  Aim[w] = sf * st_;
            Bre[w] = sf * ct_;  Bim[w] = -cf * st_;
        }

        float Lr, Li;
        {
            int s0 = lane & 1;
            Lr = s0 ? Bre[4] : Are[4];
            Li = s0 ? Bim[4] : Aim[4];
            #pragma unroll
            for (int i = 1; i < 5; i++) {
                int w = 4 - i;
                int s = (lane >> i) & 1;
                float xr = s ? Bre[w] : Are[w];
                float xi = s ? Bim[w] : Aim[w];
                float nr, ni;
                cmul(nr, ni, Lr, Li, xr, xi);
                Lr = nr; Li = ni;
            }
        }
        float Tr[4], Ti[4];
        #pragma unroll
        for (int j = 0; j < 4; j++) {
            float xr = (j & 1) ? Bre[7] : Are[7];
            float xi = (j & 1) ? Bim[7] : Aim[7];
            float yr = (j & 2) ? Bre[6] : Are[6];
            float yi = (j & 2) ? Bim[6] : Aim[6];
            cmul(Tr[j], Ti[j], xr, xi, yr, yi);
        }
        u64 st[8];
        #pragma unroll
        for (int r = 0; r < 8; r++) {
            float ur = (r & 4) ? Bre[5] : Are[5];
            float ui = (r & 4) ? Bim[5] : Aim[5];
            float Rr, Ri, fr, fi;
            cmul(Rr, Ri, Tr[r & 3], Ti[r & 3], ur, ui);
            cmul(fr, fi, Lr, Li, Rr, Ri);
            st[r] = pk(fr, fi);
        }

        // ---- d1 RY sweep (CNOT chains fused as Gray remap), packed f32x2 ----
        #pragma unroll
        for (int w = 0; w < 8; w++) {
            const int p  = 7 - w;
            const float rc = sRc[wid][w];
            const float rs = sRs[wid][w];
            const int pairMask = (p > 0) ? (3 << (p - 1)) : 1;
            const int sideMask = (0xFF << p) & 0xFF;
            const int laneXor  = pairMask >> 3;
            const int localXor = pairMask & 7;
            const int laneSide = (sideMask >> 3) & 31;
            const int rSide    = sideMask & 7;

            float base = (__popc(lane & laneSide) & 1) ? rs : -rs;
            u64 rc2 = pk(rc, rc);
            u64 bp  = pk(base, base);
            u64 bn  = pk(-base, -base);

            u64 prt[8];
            #pragma unroll
            for (int r = 0; r < 8; r++) {
                u64 v = st[r ^ localXor];
                if (laneXor) v = __shfl_xor_sync(0xffffffffu, v, laneXor);
                prt[r] = v;
            }
            #pragma unroll
            for (int r = 0; r < 8; r++) {
                const int pir = __popc(r & rSide) & 1;   // compile-time
                u64 coef = pir ? bn : bp;
                u64 tmp;
                MUL2(tmp, rc2, st[r]);
                FMA2(st[r], coef, prt[r], tmp);
            }
        }

        // ---- Z expectations ----
        float prob[8];
        #pragma unroll
        for (int r = 0; r < 8; r++) {
            float re, im;
            upk(st[r], re, im);
            prob[r] = fmaf(re, re, im * im);
        }
        // local 3-bit Walsh: masks 0 (SA), 2 (S1), 4 (S2), 5 (S0)
        float u0 = prob[0] + prob[4], v0_ = prob[0] - prob[4];
        float u1 = prob[1] + prob[5], v1_ = prob[1] - prob[5];
        float u2 = prob[2] + prob[6], v2_ = prob[2] - prob[6];
        float u3 = prob[3] + prob[7], v3_ = prob[3] - prob[7];
        float SA = (u0 + u1) + (u2 + u3);
        float S1 = (u0 + u1) - (u2 + u3);
        float S2 = (v0_ + v1_) + (v2_ + v3_);
        float S0 = (v0_ - v1_) + (v2_ - v3_);

        // pre-apply lane signs: v[p] = (+-) S_{local(p)}; z_p = sum over lanes
        int pA = __popc(lane & 0x0A) & 1;
        int pB = __popc(lane & 0x15) & 1;
        int pC = __popc(lane & 0x14) & 1;
        int pD = (lane >> 3) & 1;
        int pE = (lane >> 4) & 1;
        float v0 = pA ? -S0 : S0;   // p=0
        float v1 = pB ? -S1 : S1;   // p=1
        float v2 = pA ? -S2 : S2;   // p=2
        float v3 = pB ? -SA : SA;   // p=3
        float v4 = pA ? -SA : SA;   // p=4
        float v5 = pC ? -SA : SA;   // p=5
        float v6 = pD ? -SA : SA;   // p=6
        float v7 = pE ? -SA : SA;   // p=7

        // multi-value reduction: 8 sums over 32 lanes in 9 shuffles
        {
            const unsigned FM = 0xffffffffu;
            int t0 = lane & 1;
            float s0 = t0 ? v0 : v1, s1 = t0 ? v2 : v3;
            float s2 = t0 ? v4 : v5, s3 = t0 ? v6 : v7;
            float r0 = __shfl_xor_sync(FM, s0, 1);
            float r1 = __shfl_xor_sync(FM, s1, 1);
            float r2 = __shfl_xor_sync(FM, s2, 1);
            float r3 = __shfl_xor_sync(FM, s3, 1);
            float w0_ = (t0 ? v1 : v0) + r0;   // j = 2i + t0
            float w1_ = (t0 ? v3 : v2) + r1;
            float w2_ = (t0 ? v5 : v4) + r2;
            float w3_ = (t0 ? v7 : v6) + r3;

            int t1 = (lane >> 1) & 1;
            float s4 = t1 ? w0_ : w1_, s5 = t1 ? w2_ : w3_;
            float r4 = __shfl_xor_sync(FM, s4, 2);
            float r5 = __shfl_xor_sync(FM, s5, 2);
            float x0_ = (t1 ? w1_ : w0_) + r4;  // j = 4s + 2*t1 + t0
            float x1_ = (t1 ? w3_ : w2_) + r5;

            int t2 = (lane >> 2) & 1;
            float s6 = t2 ? x0_ : x1_;
            float r6 = __shfl_xor_sync(FM, s6, 4);
            float y = (t2 ? x1_ : x0_) + r6;    // j = lane & 7 = p

            y += __shfl_xor_sync(FM, y, 8);
            y += __shfl_xor_sync(FM, y, 16);

            if (lane < 8)
                ((float*)&zsh4[buf][0])[(7 - lane) * 4 + wid] = y;  // wire 7-p, gate wid
        }
        __syncthreads();   // C: zsh visible

        // ---- gate projections + LSTM update (thread tid <-> hidden unit tid) ----
        {
            float accf = bfr, acci = bir, accg = bgr, acco = bor;
            #pragma unroll
            for (int w = 0; w < NQ; w++) {
                float4 zz = zsh4[buf][w];
                float4 ww = sWg4[w][tid];
                accf = fmaf(zz.x, ww.x, accf);
                acci = fmaf(zz.y, ww.y, acci);
                accg = fmaf(zz.z, ww.z, accg);
                acco = fmaf(zz.w, ww.w, acco);
            }
            float fg = __fdividef(1.f, 1.f + __expf(-accf));
            float ig = __fdividef(1.f, 1.f + __expf(-acci));
            float e2 = __expf(2.f * accg);
            float gg = __fdividef(e2 - 1.f, e2 + 1.f);
            float og = __fdividef(1.f, 1.f + __expf(-acco));

            creg = fmaf(fg, creg, ig * gg);
            float e2c = __expf(2.f * creg);
            hreg = og * __fdividef(e2c - 1.f, e2c + 1.f);

            out[(size_t)t * BATCH * HIDDEN + (size_t)b * HIDDEN + tid] = hreg;
        }
        xcur = xnext;
        // no tail sync: next iteration uses the other buffer
    }

    // ---- final hx, cx ----
    size_t base = (size_t)SEQ * BATCH * HIDDEN;
    out[base + (size_t)b * HIDDEN + tid] = hreg;
    out[base + (size_t)BATCH * HIDDEN + (size_t)b * HIDDEN + tid] = creg;
}

extern "C" void kernel_launch(void* const* d_in, const int* in_sizes, int n_in,
                              void* d_out, int out_size)
{
    const float* inputs = (const float*)d_in[0];
    const float* Wq     = (const float*)d_in[1];
    const float* bq     = (const float*)d_in[2];
    const float* pf     = (const float*)d_in[3];
    const float* pi_    = (const float*)d_in[4];
    const float* pg     = (const float*)d_in[5];
    const float* po     = (const float*)d_in[6];
    const float* Wf     = (const float*)d_in[7];
    const float* bf     = (const float*)d_in[8];
    const float* Wi     = (const float*)d_in[9];
    const float* bi     = (const float*)d_in[10];
    const float* Wg     = (const float*)d_in[11];
    const float* bg     = (const float*)d_in[12];
    const float* Wo     = (const float*)d_in[13];
    const float* bo     = (const float*)d_in[14];
    float* out = (float*)d_out;

    qlstm_all<<<BATCH, 128>>>(inputs, Wq, bq, pf, pi_, pg, po,
                              Wf, bf, Wi, bi, Wg, bg, Wo, bo, out);
}

// round 7
// speedup vs baseline: 1.7931x; 1.0667x over previous
#include <cuda_runtime.h>

#define SEQ       128
#define BATCH     512
#define INPUT_DIM 128
#define HIDDEN    128
#define NQ        8

typedef unsigned long long u64;

__device__ __forceinline__ u64 pk(float lo, float hi) {
    u64 r; asm("mov.b64 %0, {%1, %2};" : "=l"(r) : "f"(lo), "f"(hi)); return r;
}
__device__ __forceinline__ void upk(u64 v, float& lo, float& hi) {
    asm("mov.b64 {%0, %1}, %2;" : "=f"(lo), "=f"(hi) : "l"(v));
}
#define FMA2(o,a,b,c) asm("fma.rn.f32x2 %0, %1, %2, %3;" : "=l"(o) : "l"(a), "l"(b), "l"(c))

__device__ __forceinline__ void cmul(float& orr, float& oi,
                                     float ar, float ai, float br, float bi) {
    orr = fmaf(ar, br, -ai * bi);
    oi  = fmaf(ar, bi,  ai * br);
}

__global__ __launch_bounds__(128, 4)
void qlstm_all(const float* __restrict__ inputs,  // [SEQ,BATCH,INPUT_DIM]
               const float* __restrict__ Wq,      // [32,256] rows 0..7 used
               const float* __restrict__ bq,
               const float* __restrict__ pf,
               const float* __restrict__ pi_,
               const float* __restrict__ pg,
               const float* __restrict__ po,
               const float* __restrict__ Wf, const float* __restrict__ bf,
               const float* __restrict__ Wi, const float* __restrict__ bi,
               const float* __restrict__ Wg, const float* __restrict__ bg,
               const float* __restrict__ Wo, const float* __restrict__ bo,
               float* __restrict__ out)
{
    const int b    = blockIdx.x;
    const int tid  = threadIdx.x;
    const int wid  = tid >> 5;
    const int lane = tid & 31;

    __shared__ float4 sWq4[512];            // 8KB: rows 0..7 of Wq as float4
    __shared__ float4 sWg4[NQ][HIDDEN];     // 16KB: (f,i,g,o)*scale2 per (wire,hidden)
    __shared__ float sC0[4][NQ], sS0[4][NQ];   // d0 RY constants (folded into init)
    __shared__ float sRc[4][NQ], sRs[4][NQ];   // d1 RY constants
    __shared__ float sTau[4][NQ];              // tan(phi/2) for d1 layer
    __shared__ float sSc2[4];                  // (prod rc)^2 per gate
    __shared__ float sBq[8];
    __shared__ float4 comb4[2][64];         // double-buffered [x;h]
    __shared__ float4 qin4[2][2];           // 8 q_in values as 2 float4
    __shared__ float4 zsh4[2][NQ];          // per wire: (zf,zi,zg,zo)

    // ---------- one-time setup ----------
    {
        const float4* Wq4 = (const float4*)Wq;
        for (int i = tid; i < 512; i += 128) sWq4[i] = Wq4[i];
        if (tid < 8) sBq[tid] = bq[tid];

        const float* prm = (wid == 0) ? pf : (wid == 1) ? pi_ : (wid == 2) ? pg : po;
        if (lane < 16) {
            float c, s;
            __sincosf(0.5f * prm[lane], &s, &c);
            if (lane < 8) { sC0[wid][lane] = c;     sS0[wid][lane] = s;     }
            else          { sRc[wid][lane - 8] = c; sRs[wid][lane - 8] = s; }
        }
        __syncthreads();
        if (lane < 8) sTau[wid][lane] = sRs[wid][lane] / sRc[wid][lane];
        if (lane == 0) {
            float p = 1.f;
            #pragma unroll
            for (int w = 0; w < NQ; w++) p *= sRc[wid][w];
            sSc2[wid] = p * p;
        }
        __syncthreads();
        float scf = sSc2[0], sci = sSc2[1], scg = sSc2[2], sco = sSc2[3];
        for (int i = tid; i < HIDDEN * NQ; i += 128) {
            int h = i >> 3, w = i & 7;
            sWg4[w][h] = make_float4(Wf[i] * scf, Wi[i] * sci,
                                     Wg[i] * scg, Wo[i] * sco);
        }
    }

    const float bfr = bf[tid], bir = bi[tid], bgr = bg[tid], bor = bo[tid];

    float hreg = 0.f, creg = 0.f;
    const float* inb = inputs + (size_t)b * INPUT_DIM;
    float xcur = inb[tid];                 // prefetch t=0
    __syncthreads();

    for (int t = 0; t < SEQ; t++) {
        const int buf = t & 1;

        {
            float* combS = (float*)comb4[buf];
            combS[tid]       = xcur;
            combS[128 + tid] = hreg;
        }
        float xnext = 0.f;
        if (t + 1 < SEQ) xnext = inb[(size_t)(t + 1) * BATCH * INPUT_DIM + tid];
        __syncthreads();   // A: comb visible

        // ---- q_in = combined @ Wq[:8].T + bq[:8] (warp wid -> rows 2wid, 2wid+1) ----
        {
            const float4* w0 = sWq4 + (2 * wid) * 64;
            const float4* w1 = w0 + 64;
            float4 c0 = comb4[buf][lane];
            float4 c1 = comb4[buf][32 + lane];
            float4 wa = w0[lane], wb = w0[32 + lane];
            float4 wc = w1[lane], wd = w1[32 + lane];
            float a0 = c0.x * wa.x;
            a0 = fmaf(c0.y, wa.y, a0); a0 = fmaf(c0.z, wa.z, a0); a0 = fmaf(c0.w, wa.w, a0);
            a0 = fmaf(c1.x, wb.x, a0); a0 = fmaf(c1.y, wb.y, a0);
            a0 = fmaf(c1.z, wb.z, a0); a0 = fmaf(c1.w, wb.w, a0);
            float a1 = c0.x * wc.x;
            a1 = fmaf(c0.y, wc.y, a1); a1 = fmaf(c0.z, wc.z, a1); a1 = fmaf(c0.w, wc.w, a1);
            a1 = fmaf(c1.x, wd.x, a1); a1 = fmaf(c1.y, wd.y, a1);
            a1 = fmaf(c1.z, wd.z, a1); a1 = fmaf(c1.w, wd.w, a1);
            // pair-interleaved reduction: 6 shfl for both sums
            const unsigned FM = 0xffffffffu;
            int t0 = lane & 1;
            float s  = t0 ? a0 : a1;
            float rr = __shfl_xor_sync(FM, s, 1);
            float v  = (t0 ? a1 : a0) + rr;     // even lanes: a0-partial, odd: a1-partial
            #pragma unroll
            for (int o = 2; o <= 16; o <<= 1) v += __shfl_xor_sync(FM, v, o);
            if (lane < 2) {
                float* qq = (float*)qin4[buf];
                qq[2 * wid + lane] = v + sBq[2 * wid + lane];
            }
        }
        __syncthreads();   // B: qin visible

        float4 q03 = qin4[buf][0], q47 = qin4[buf][1];
        const float q[8] = {q03.x, q03.y, q03.z, q03.w, q47.x, q47.y, q47.z, q47.w};

        // ---- init: product state after RX + first RY layer (folded) ----
        // A_w = (cf*ct, sf*st), B_w = (sf*ct, -cf*st); k=(lane<<3)|r, wire w <-> bit 7-w
        float Are[NQ], Aim[NQ], Bre[NQ], Bim[NQ];
        #pragma unroll
        for (int w = 0; w < NQ; w++) {
            float st_, ct_;
            __sincosf(0.5f * q[w], &st_, &ct_);
            float cf = sC0[wid][w], sf = sS0[wid][w];
            Are[w] = cf * ct_;  Aim[w] = sf * st_;
            Bre[w] = sf * ct_;  Bim[w] = -cf * st_;
        }

        // lane product over wires 4..0 (lane bit i <-> wire 4-i), tree form
        float Lr, Li;
        {
            float e0r, e0i, e1r, e1i, m0r, m0i, m1r, m1i;
            int s0 = lane & 1, s1 = (lane >> 1) & 1;
            int s2 = (lane >> 2) & 1, s3 = (lane >> 3) & 1, s4 = (lane >> 4) & 1;
            cmul(m0r, m0i, s0 ? Bre[4] : Are[4], s0 ? Bim[4] : Aim[4],
                           s1 ? Bre[3] : Are[3], s1 ? Bim[3] : Aim[3]);
            cmul(m1r, m1i, s2 ? Bre[2] : Are[2], s2 ? Bim[2] : Aim[2],
                           s3 ? Bre[1] : Are[1], s3 ? Bim[1] : Aim[1]);
            cmul(e0r, e0i, m0r, m0i, m1r, m1i);
            e1r = s4 ? Bre[0] : Are[0]; e1i = s4 ? Bim[0] : Aim[0];
            cmul(Lr, Li, e0r, e0i, e1r, e1i);
        }
        float Tr[4], Ti[4];
        #pragma unroll
        for (int j = 0; j < 4; j++) {
            float xr = (j & 1) ? Bre[7] : Are[7];
            float xi = (j & 1) ? Bim[7] : Aim[7];
            float yr = (j & 2) ? Bre[6] : Are[6];
            float yi = (j & 2) ? Bim[6] : Aim[6];
            cmul(Tr[j], Ti[j], xr, xi, yr, yi);
        }
        u64 st[8];
        #pragma unroll
        for (int r = 0; r < 8; r++) {
            float ur = (r & 4) ? Bre[5] : Are[5];
            float ui = (r & 4) ? Bim[5] : Aim[5];
            float Rr, Ri, fr, fi;
            cmul(Rr, Ri, Tr[r & 3], Ti[r & 3], ur, ui);
            cmul(fr, fi, Lr, Li, Rr, Ri);
            st[r] = pk(fr, fi);
        }

        // ---- d1 RY sweep, tan-form butterflies (normalization folded into sWg4) ----
        #pragma unroll
        for (int w = 0; w < 8; w++) {
            const int p  = 7 - w;
            const float tau = sTau[wid][w];
            const int pairMask = (p > 0) ? (3 << (p - 1)) : 1;
            const int sideMask = (0xFF << p) & 0xFF;
            const int laneXor  = pairMask >> 3;
            const int localXor = pairMask & 7;
            const int laneSide = (sideMask >> 3) & 31;
            const int rSide    = sideMask & 7;

            float base = (__popc(lane & laneSide) & 1) ? tau : -tau;
            u64 bp = pk(base, base);
            u64 bn = pk(-base, -base);

            u64 prt[8];
            #pragma unroll
            for (int r = 0; r < 8; r++) {
                u64 v = st[r ^ localXor];
                if (laneXor) v = __shfl_xor_sync(0xffffffffu, v, laneXor);
                prt[r] = v;
            }
            #pragma unroll
            for (int r = 0; r < 8; r++) {
                const int pir = __popc(r & rSide) & 1;   // compile-time
                u64 coef = pir ? bn : bp;
                FMA2(st[r], coef, prt[r], st[r]);
            }
        }

        // ---- Z expectations (on tan-scaled amplitudes; scale folded into weights) ----
        float prob[8];
        #pragma unroll
        for (int r = 0; r < 8; r++) {
            float re, im;
            upk(st[r], re, im);
            prob[r] = fmaf(re, re, im * im);
        }
        // local 3-bit Walsh: masks 0 (SA), 2 (S1), 4 (S2), 5 (S0)
        float u0 = prob[0] + prob[4], v0_ = prob[0] - prob[4];
        float u1 = prob[1] + prob[5], v1_ = prob[1] - prob[5];
        float u2 = prob[2] + prob[6], v2_ = prob[2] - prob[6];
        float u3 = prob[3] + prob[7], v3_ = prob[3] - prob[7];
        float SA = (u0 + u1) + (u2 + u3);
        float S1 = (u0 + u1) - (u2 + u3);
        float S2 = (v0_ + v1_) + (v2_ + v3_);
        float S0 = (v0_ - v1_) + (v2_ - v3_);

        // pre-apply lane signs
        int pA = __popc(lane & 0x0A) & 1;
        int pB = __popc(lane & 0x15) & 1;
        int pC = __popc(lane & 0x14) & 1;
        int pD = (lane >> 3) & 1;
        int pE = (lane >> 4) & 1;
        float v0 = pA ? -S0 : S0;   // p=0
        float v1 = pB ? -S1 : S1;   // p=1
        float v2 = pA ? -S2 : S2;   // p=2
        float v3 = pB ? -SA : SA;   // p=3
        float v4 = pA ? -SA : SA;   // p=4
        float v5 = pC ? -SA : SA;   // p=5
        float v6 = pD ? -SA : SA;   // p=6
        float v7 = pE ? -SA : SA;   // p=7

        // multi-value reduction: 8 sums over 32 lanes in 9 shuffles
        {
            const unsigned FM = 0xffffffffu;
            int t0 = lane & 1;
            float s0 = t0 ? v0 : v1, s1 = t0 ? v2 : v3;
            float s2 = t0 ? v4 : v5, s3 = t0 ? v6 : v7;
            float r0 = __shfl_xor_sync(FM, s0, 1);
            float r1 = __shfl_xor_sync(FM, s1, 1);
            float r2 = __shfl_xor_sync(FM, s2, 1);
            float r3 = __shfl_xor_sync(FM, s3, 1);
            float w0_ = (t0 ? v1 : v0) + r0;
            float w1_ = (t0 ? v3 : v2) + r1;
            float w2_ = (t0 ? v5 : v4) + r2;
            float w3_ = (t0 ? v7 : v6) + r3;

            int t1 = (lane >> 1) & 1;
            float s4 = t1 ? w0_ : w1_, s5 = t1 ? w2_ : w3_;
            float r4 = __shfl_xor_sync(FM, s4, 2);
            float r5 = __shfl_xor_sync(FM, s5, 2);
            float x0_ = (t1 ? w1_ : w0_) + r4;
            float x1_ = (t1 ? w3_ : w2_) + r5;

            int t2 = (lane >> 2) & 1;
            float s6 = t2 ? x0_ : x1_;
            float r6 = __shfl_xor_sync(FM, s6, 4);
            float y = (t2 ? x1_ : x0_) + r6;    // j = lane & 7 = p

            y += __shfl_xor_sync(FM, y, 8);
            y += __shfl_xor_sync(FM, y, 16);

            if (lane < 8)
                ((float*)&zsh4[buf][0])[(7 - lane) * 4 + wid] = y;  // wire 7-p, gate wid
        }
        __syncthreads();   // C: zsh visible

        // ---- gate projections + LSTM update (thread tid <-> hidden unit tid) ----
        {
            float accf = bfr, acci = bir, accg = bgr, acco = bor;
            #pragma unroll
            for (int w = 0; w < NQ; w++) {
                float4 zz = zsh4[buf][w];
                float4 ww = sWg4[w][tid];
                accf = fmaf(zz.x, ww.x, accf);
                acci = fmaf(zz.y, ww.y, acci);
                accg = fmaf(zz.z, ww.z, accg);
                acco = fmaf(zz.w, ww.w, acco);
            }
            float fg = __fdividef(1.f, 1.f + __expf(-accf));
            float ig = __fdividef(1.f, 1.f + __expf(-acci));
            float e2 = __expf(2.f * accg);
            float gg = __fdividef(e2 - 1.f, e2 + 1.f);
            float og = __fdividef(1.f, 1.f + __expf(-acco));

            creg = fmaf(fg, creg, ig * gg);
            float e2c = __expf(2.f * creg);
            hreg = og * __fdividef(e2c - 1.f, e2c + 1.f);

            out[(size_t)t * BATCH * HIDDEN + (size_t)b * HIDDEN + tid] = hreg;
        }
        xcur = xnext;
        // no tail sync: next iteration uses the other buffer
    }

    // ---- final hx, cx ----
    size_t base = (size_t)SEQ * BATCH * HIDDEN;
    out[base + (size_t)b * HIDDEN + tid] = hreg;
    out[base + (size_t)BATCH * HIDDEN + (size_t)b * HIDDEN + tid] = creg;
}

extern "C" void kernel_launch(void* const* d_in, const int* in_sizes, int n_in,
                              void* d_out, int out_size)
{
    const float* inputs = (const float*)d_in[0];
    const float* Wq     = (const float*)d_in[1];
    const float* bq     = (const float*)d_in[2];
    const float* pf     = (const float*)d_in[3];
    const float* pi_    = (const float*)d_in[4];
    const float* pg     = (const float*)d_in[5];
    const float* po     = (const float*)d_in[6];
    const float* Wf     = (const float*)d_in[7];
    const float* bf     = (const float*)d_in[8];
    const float* Wi     = (const float*)d_in[9];
    const float* bi     = (const float*)d_in[10];
    const float* Wg     = (const float*)d_in[11];
    const float* bg     = (const float*)d_in[12];
    const float* Wo     = (const float*)d_in[13];
    const float* bo     = (const float*)d_in[14];
    float* out = (float*)d_out;

    qlstm_all<<<BATCH, 128>>>(inputs, Wq, bq, pf, pi_, pg, po,
                              Wf, bf, Wi, bi, Wg, bg, Wo, bo, out);
}

// round 8
// speedup vs baseline: 1.8953x; 1.0570x over previous
#include <cuda_runtime.h>

#define SEQ       128
#define BATCH     512
#define INPUT_DIM 128
#define HIDDEN    128
#define NQ        8

typedef unsigned long long u64;

__device__ __forceinline__ u64 pk(float lo, float hi) {
    u64 r; asm("mov.b64 %0, {%1, %2};" : "=l"(r) : "f"(lo), "f"(hi)); return r;
}
__device__ __forceinline__ void upk(u64 v, float& lo, float& hi) {
    asm("mov.b64 {%0, %1}, %2;" : "=f"(lo), "=f"(hi) : "l"(v));
}
#define MUL2(o,a,b)   asm("mul.rn.f32x2 %0, %1, %2;"     : "=l"(o) : "l"(a), "l"(b))
#define FMA2(o,a,b,c) asm("fma.rn.f32x2 %0, %1, %2, %3;" : "=l"(o) : "l"(a), "l"(b), "l"(c))

__device__ __forceinline__ void cmul(float& orr, float& oi,
                                     float ar, float ai, float br, float bi) {
    orr = fmaf(ar, br, -ai * bi);
    oi  = fmaf(ar, bi,  ai * br);
}

__global__ __launch_bounds__(128, 4)
void qlstm_all(const float* __restrict__ inputs,  // [SEQ,BATCH,INPUT_DIM]
               const float* __restrict__ Wq,      // [32,256] rows 0..7 used
               const float* __restrict__ bq,
               const float* __restrict__ pf,
               const float* __restrict__ pi_,
               const float* __restrict__ pg,
               const float* __restrict__ po,
               const float* __restrict__ Wf, const float* __restrict__ bf,
               const float* __restrict__ Wi, const float* __restrict__ bi,
               const float* __restrict__ Wg, const float* __restrict__ bg,
               const float* __restrict__ Wo, const float* __restrict__ bo,
               float* __restrict__ out)
{
    const int b    = blockIdx.x;
    const int tid  = threadIdx.x;
    const int wid  = tid >> 5;
    const int lane = tid & 31;

    __shared__ float4 sWq4[512];            // 8KB: rows 0..7 of Wq as float4
    __shared__ float4 sWg4[NQ][HIDDEN];     // 16KB: (f,i,g,o)*scale2 per (wire,hidden)
    __shared__ float sSc2[4];               // (prod rc)^2 per gate
    __shared__ float sBq[8];
    __shared__ float4 comb4[2][64];         // double-buffered [x;h]
    __shared__ float2 qsc[2][8];            // (cos, sin) of q_in/2 per wire
    __shared__ float4 zsh4[2][NQ];          // per wire: (zf,zi,zg,zo)

    // ---------- one-time setup ----------
    // per-warp gate constants, held in REGISTERS across the whole loop
    u64 kA[NQ], kB[NQ];    // pk(cf,sf), pk(sf,cf) for d0 layer
    float rtau[NQ];        // tan(phi/2) for d1 layer
    {
        const float4* Wq4 = (const float4*)Wq;
        for (int i = tid; i < 512; i += 128) sWq4[i] = Wq4[i];
        if (tid < 8) sBq[tid] = bq[tid];

        const float* prm = (wid == 0) ? pf : (wid == 1) ? pi_ : (wid == 2) ? pg : po;
        float prodc = 1.f;
        #pragma unroll
        for (int w = 0; w < NQ; w++) {
            float c, s;
            __sincosf(0.5f * prm[w], &s, &c);        // d0
            kA[w] = pk(c, s);
            kB[w] = pk(s, c);
            __sincosf(0.5f * prm[NQ + w], &s, &c);   // d1
            rtau[w] = s / c;
            prodc *= c;
        }
        if (lane == 0) sSc2[wid] = prodc * prodc;
        __syncthreads();
        float scf = sSc2[0], sci = sSc2[1], scg = sSc2[2], sco = sSc2[3];
        for (int i = tid; i < HIDDEN * NQ; i += 128) {
            int h = i >> 3, w = i & 7;
            sWg4[w][h] = make_float4(Wf[i] * scf, Wi[i] * sci,
                                     Wg[i] * scg, Wo[i] * sco);
        }
    }

    const float bfr = bf[tid], bir = bi[tid], bgr = bg[tid], bor = bo[tid];

    float hreg = 0.f, creg = 0.f;
    const float* inb = inputs + (size_t)b * INPUT_DIM;
    float xcur = inb[tid];                 // prefetch t=0
    __syncthreads();

    for (int t = 0; t < SEQ; t++) {
        const int buf = t & 1;

        {
            float* combS = (float*)comb4[buf];
            combS[tid]       = xcur;
            combS[128 + tid] = hreg;
        }
        float xnext = 0.f;
        if (t + 1 < SEQ) xnext = inb[(size_t)(t + 1) * BATCH * INPUT_DIM + tid];
        __syncthreads();   // A: comb visible

        // ---- q_in = combined @ Wq[:8].T + bq ; producer also does sincos ----
        {
            const float4* w0 = sWq4 + (2 * wid) * 64;
            const float4* w1 = w0 + 64;
            float4 c0 = comb4[buf][lane];
            float4 c1 = comb4[buf][32 + lane];
            float4 wa = w0[lane], wb = w0[32 + lane];
            float4 wc = w1[lane], wd = w1[32 + lane];
            float a0 = c0.x * wa.x;
            a0 = fmaf(c0.y, wa.y, a0); a0 = fmaf(c0.z, wa.z, a0); a0 = fmaf(c0.w, wa.w, a0);
            a0 = fmaf(c1.x, wb.x, a0); a0 = fmaf(c1.y, wb.y, a0);
            a0 = fmaf(c1.z, wb.z, a0); a0 = fmaf(c1.w, wb.w, a0);
            float a1 = c0.x * wc.x;
            a1 = fmaf(c0.y, wc.y, a1); a1 = fmaf(c0.z, wc.z, a1); a1 = fmaf(c0.w, wc.w, a1);
            a1 = fmaf(c1.x, wd.x, a1); a1 = fmaf(c1.y, wd.y, a1);
            a1 = fmaf(c1.z, wd.z, a1); a1 = fmaf(c1.w, wd.w, a1);
            // pair-interleaved reduction: 6 shfl for both sums
            const unsigned FM = 0xffffffffu;
            int t0 = lane & 1;
            float s  = t0 ? a0 : a1;
            float rr = __shfl_xor_sync(FM, s, 1);
            float v  = (t0 ? a1 : a0) + rr;     // even lanes: a0 total, odd: a1 total
            #pragma unroll
            for (int o = 2; o <= 16; o <<= 1) v += __shfl_xor_sync(FM, v, o);
            if (lane < 2) {
                float qv = v + sBq[2 * wid + lane];
                float sq, cq;
                __sincosf(0.5f * qv, &sq, &cq);
                qsc[buf][2 * wid + lane] = make_float2(cq, sq);
            }
        }
        __syncthreads();   // B: qsc visible

        // ---- build per-wire A/B inline: A=(cf*ct,sf*st), B=(sf*ct,-cf*st) ----
        #define MAKE_AB(w, Av, Bv)                                   \
            {                                                        \
                float2 cs_ = qsc[buf][w];                            \
                u64 cp_ = pk(cs_.x, cs_.y);                          \
                u64 cm_ = pk(cs_.x, -cs_.y);                         \
                MUL2(Av, kA[w], cp_);                                \
                MUL2(Bv, kB[w], cm_);                                \
            }

        // lane product over wires 4..0 (lane bit i <-> wire 4-i), tree form
        float Lr, Li;
        {
            int s0 = lane & 1, s1 = (lane >> 1) & 1;
            int s2 = (lane >> 2) & 1, s3 = (lane >> 3) & 1, s4 = (lane >> 4) & 1;
            u64 A_, B_;
            float xr, xi, yr, yi, m0r, m0i, m1r, m1i, e0r, e0i;
            MAKE_AB(4, A_, B_); upk(s0 ? B_ : A_, xr, xi);
            MAKE_AB(3, A_, B_); upk(s1 ? B_ : A_, yr, yi);
            cmul(m0r, m0i, xr, xi, yr, yi);
            MAKE_AB(2, A_, B_); upk(s2 ? B_ : A_, xr, xi);
            MAKE_AB(1, A_, B_); upk(s3 ? B_ : A_, yr, yi);
            cmul(m1r, m1i, xr, xi, yr, yi);
            cmul(e0r, e0i, m0r, m0i, m1r, m1i);
            MAKE_AB(0, A_, B_); upk(s4 ? B_ : A_, xr, xi);
            cmul(Lr, Li, e0r, e0i, xr, xi);
        }

        // T over wires 7,6 (r bits 0,1); factored LT = L*T; then x wire5 (r bit2)
        u64 st[8];
        {
            float A7r, A7i, B7r, B7i, A6r, A6i, B6r, B6i, A5r, A5i, B5r, B5i;
            u64 A_, B_;
            MAKE_AB(7, A_, B_); upk(A_, A7r, A7i); upk(B_, B7r, B7i);
            MAKE_AB(6, A_, B_); upk(A_, A6r, A6i); upk(B_, B6r, B6i);
            MAKE_AB(5, A_, B_); upk(A_, A5r, A5i); upk(B_, B5r, B5i);

            float LTr[4], LTi[4];
            #pragma unroll
            for (int j = 0; j < 4; j++) {
                float xr = (j & 1) ? B7r : A7r, xi = (j & 1) ? B7i : A7i;
                float yr = (j & 2) ? B6r : A6r, yi = (j & 2) ? B6i : A6i;
                float tr, ti;
                cmul(tr, ti, xr, xi, yr, yi);
                cmul(LTr[j], LTi[j], Lr, Li, tr, ti);
            }
            #pragma unroll
            for (int r = 0; r < 8; r++) {
                float ur = (r & 4) ? B5r : A5r, ui = (r & 4) ? B5i : A5i;
                float fr, fi;
                cmul(fr, fi, LTr[r & 3], LTi[r & 3], ur, ui);
                st[r] = pk(fr, fi);
            }
        }
        #undef MAKE_AB

        // ---- d1 RY sweep, tan-form butterflies (normalization folded into sWg4) ----
        #pragma unroll
        for (int w = 0; w < 8; w++) {
            const int p  = 7 - w;
            const float tau = rtau[w];
            const int pairMask = (p > 0) ? (3 << (p - 1)) : 1;
            const int sideMask = (0xFF << p) & 0xFF;
            const int laneXor  = pairMask >> 3;
            const int localXor = pairMask & 7;
            const int laneSide = (sideMask >> 3) & 31;
            const int rSide    = sideMask & 7;

            float base = (__popc(lane & laneSide) & 1) ? tau : -tau;
            u64 bp = pk(base, base);
            u64 bn = pk(-base, -base);

            u64 prt[8];
            #pragma unroll
            for (int r = 0; r < 8; r++) {
                u64 v = st[r ^ localXor];
                if (laneXor) v = __shfl_xor_sync(0xffffffffu, v, laneXor);
                prt[r] = v;
            }
            #pragma unroll
            for (int r = 0; r < 8; r++) {
                const int pir = __popc(r & rSide) & 1;   // compile-time
                u64 coef = pir ? bn : bp;
                FMA2(st[r], coef, prt[r], st[r]);
            }
        }

        // ---- Z expectations (on tan-scaled amplitudes; scale folded into weights) ----
        float prob[8];
        #pragma unroll
        for (int r = 0; r < 8; r++) {
            float re, im;
            upk(st[r], re, im);
            prob[r] = fmaf(re, re, im * im);
        }
        // local 3-bit Walsh: masks 0 (SA), 2 (S1), 4 (S2), 5 (S0)
        float u0 = prob[0] + prob[4], v0_ = prob[0] - prob[4];
        float u1 = prob[1] + prob[5], v1_ = prob[1] - prob[5];
        float u2 = prob[2] + prob[6], v2_ = prob[2] - prob[6];
        float u3 = prob[3] + prob[7], v3_ = prob[3] - prob[7];
        float SA = (u0 + u1) + (u2 + u3);
        float S1 = (u0 + u1) - (u2 + u3);
        float S2 = (v0_ + v1_) + (v2_ + v3_);
        float S0 = (v0_ - v1_) + (v2_ - v3_);

        // pre-apply lane signs
        int pA = __popc(lane & 0x0A) & 1;
        int pB = __popc(lane & 0x15) & 1;
        int pC = __popc(lane & 0x14) & 1;
        int pD = (lane >> 3) & 1;
        int pE = (lane >> 4) & 1;
        float v0 = pA ? -S0 : S0;   // p=0
        float v1 = pB ? -S1 : S1;   // p=1
        float v2 = pA ? -S2 : S2;   // p=2
        float v3 = pB ? -SA : SA;   // p=3
        float v4 = pA ? -SA : SA;   // p=4
        float v5 = pC ? -SA : SA;   // p=5
        float v6 = pD ? -SA : SA;   // p=6
        float v7 = pE ? -SA : SA;   // p=7

        // multi-value reduction: 8 sums over 32 lanes in 9 shuffles
        {
            const unsigned FM = 0xffffffffu;
            int t0 = lane & 1;
            float s0 = t0 ? v0 : v1, s1 = t0 ? v2 : v3;
            float s2 = t0 ? v4 : v5, s3 = t0 ? v6 : v7;
            float r0 = __shfl_xor_sync(FM, s0, 1);
            float r1 = __shfl_xor_sync(FM, s1, 1);
            float r2 = __shfl_xor_sync(FM, s2, 1);
            float r3 = __shfl_xor_sync(FM, s3, 1);
            float w0_ = (t0 ? v1 : v0) + r0;
            float w1_ = (t0 ? v3 : v2) + r1;
            float w2_ = (t0 ? v5 : v4) + r2;
            float w3_ = (t0 ? v7 : v6) + r3;

            int t1 = (lane >> 1) & 1;
            float s4 = t1 ? w0_ : w1_, s5 = t1 ? w2_ : w3_;
            float r4 = __shfl_xor_sync(FM, s4, 2);
            float r5 = __shfl_xor_sync(FM, s5, 2);
            float x0_ = (t1 ? w1_ : w0_) + r4;
            float x1_ = (t1 ? w3_ : w2_) + r5;

            int t2 = (lane >> 2) & 1;
            float s6 = t2 ? x0_ : x1_;
            float r6 = __shfl_xor_sync(FM, s6, 4);
            float y = (t2 ? x1_ : x0_) + r6;    // j = lane & 7 = p

            y += __shfl_xor_sync(FM, y, 8);
            y += __shfl_xor_sync(FM, y, 16);

            if (lane < 8)
                ((float*)&zsh4[buf][0])[(7 - lane) * 4 + wid] = y;  // wire 7-p, gate wid
        }
        __syncthreads();   // C: zsh visible

        // ---- gate projections + LSTM update (thread tid <-> hidden unit tid) ----
        {
            float accf = bfr, acci = bir, accg = bgr, acco = bor;
            #pragma unroll
            for (int w = 0; w < NQ; w++) {
                float4 zz = zsh4[buf][w];
                float4 ww = sWg4[w][tid];
                accf = fmaf(zz.x, ww.x, accf);
                acci = fmaf(zz.y, ww.y, acci);
                accg = fmaf(zz.z, ww.z, accg);
                acco = fmaf(zz.w, ww.w, acco);
            }
            float fg = __fdividef(1.f, 1.f + __expf(-accf));
            float ig = __fdividef(1.f, 1.f + __expf(-acci));
            float e2 = __expf(2.f * accg);
            float gg = __fdividef(e2 - 1.f, e2 + 1.f);
            float og = __fdividef(1.f, 1.f + __expf(-acco));

            creg = fmaf(fg, creg, ig * gg);
            float e2c = __expf(2.f * creg);
            hreg = og * __fdividef(e2c - 1.f, e2c + 1.f);

            out[(size_t)t * BATCH * HIDDEN + (size_t)b * HIDDEN + tid] = hreg;
        }
        xcur = xnext;
        // no tail sync: next iteration uses the other buffer
    }

    // ---- final hx, cx ----
    size_t base = (size_t)SEQ * BATCH * HIDDEN;
    out[base + (size_t)b * HIDDEN + tid] = hreg;
    out[base + (size_t)BATCH * HIDDEN + (size_t)b * HIDDEN + tid] = creg;
}

extern "C" void kernel_launch(void* const* d_in, const int* in_sizes, int n_in,
                              void* d_out, int out_size)
{
    const float* inputs = (const float*)d_in[0];
    const float* Wq     = (const float*)d_in[1];
    const float* bq     = (const float*)d_in[2];
    const float* pf     = (const float*)d_in[3];
    const float* pi_    = (const float*)d_in[4];
    const float* pg     = (const float*)d_in[5];
    const float* po     = (const float*)d_in[6];
    const float* Wf     = (const float*)d_in[7];
    const float* bf     = (const float*)d_in[8];
    const float* Wi     = (const float*)d_in[9];
    const float* bi     = (const float*)d_in[10];
    const float* Wg     = (const float*)d_in[11];
    const float* bg     = (const float*)d_in[12];
    const float* Wo     = (const float*)d_in[13];
    const float* bo     = (const float*)d_in[14];
    float* out = (float*)d_out;

    qlstm_all<<<BATCH, 128>>>(inputs, Wq, bq, pf, pi_, pg, po,
                              Wf, bf, Wi, bi, Wg, bg, Wo, bo, out);
}